// round 5
// baseline (speedup 1.0000x reference)
#include <cuda_runtime.h>
#include <cuda_bf16.h>

#define NN 50000
#define NE 800000
#define DD 128

// ---------------- scratch (static __device__; referenced ONLY in device code) ----
__device__ int   g_is64;             // 1 if edge_index is int64, 0 if int32
__device__ int   g_row[NE];          // edge sources  (int32, converted)
__device__ int   g_col[NE];          // edge dests    (int32, converted)
__device__ float g_deg[NN];
__device__ float g_dis[NN];          // 1/sqrt(deg)
__device__ int   g_cnt[NN];          // incoming-edge count
__device__ int   g_offs[NN];         // CSR offsets (exclusive scan of cnt)
__device__ int   g_pos[NN];          // build cursor
__device__ int   g_src[NE];          // CSR: source node per slot
__device__ float g_nrm[NE];          // CSR: norm per slot
__device__ float g_h[NN * DD];       // GEMM output (reused per layer)
__device__ float g_a1[NN * DD];      // layer-1 aggregate output

// ---------------- dtype detection + conversion ----------------
__global__ void k_detect(const void* ei) {
    // single block; sample first 1024 int64-interpreted values (8KB, in-bounds
    // for both int32 (6.4MB) and int64 (12.8MB) buffers).
    __shared__ int bad;
    if (threadIdx.x == 0) bad = 0;
    __syncthreads();
    const long long* p = (const long long*)ei;
    for (int i = threadIdx.x; i < 1024; i += blockDim.x) {
        long long v = p[i];
        if (v < 0 || v >= NN) atomicOr(&bad, 1);
    }
    __syncthreads();
    if (threadIdx.x == 0) g_is64 = bad ? 0 : 1;
}

__global__ void k_convert(const void* ei) {
    int e = blockIdx.x * blockDim.x + threadIdx.x;
    if (e < NE) {
        if (g_is64) {
            const long long* p = (const long long*)ei;
            g_row[e] = (int)p[e];
            g_col[e] = (int)p[NE + e];
        } else {
            const int* p = (const int*)ei;
            g_row[e] = p[e];
            g_col[e] = p[NE + e];
        }
    }
}

// ---------------- prep ----------------
__global__ void k_init() {
    int i = blockIdx.x * blockDim.x + threadIdx.x;
    if (i < NN) { g_deg[i] = 1.0f; g_cnt[i] = 0; }   // self-loop weight 1
}

__global__ void k_deg_accum(const float* __restrict__ ew) {
    int e = blockIdx.x * blockDim.x + threadIdx.x;
    if (e < NE) {
        int c = g_col[e];
        atomicAdd(&g_deg[c], ew[e]);
        atomicAdd(&g_cnt[c], 1);
    }
}

__global__ void k_dis() {
    int i = blockIdx.x * blockDim.x + threadIdx.x;
    if (i < NN) {
        float d = g_deg[i];
        g_dis[i] = (d > 0.0f) ? rsqrtf(d) : 0.0f;
        g_pos[i] = 0;
    }
}

// single-block exclusive scan of g_cnt -> g_offs
__global__ __launch_bounds__(1024) void k_scan() {
    __shared__ int sdata[1024];
    __shared__ int carry;
    if (threadIdx.x == 0) carry = 0;
    __syncthreads();
    for (int base = 0; base < NN; base += 1024) {
        int i = base + threadIdx.x;
        int v = (i < NN) ? g_cnt[i] : 0;
        sdata[threadIdx.x] = v;
        __syncthreads();
        for (int off = 1; off < 1024; off <<= 1) {
            int t = (threadIdx.x >= off) ? sdata[threadIdx.x - off] : 0;
            __syncthreads();
            sdata[threadIdx.x] += t;
            __syncthreads();
        }
        if (i < NN) g_offs[i] = carry + sdata[threadIdx.x] - v;   // exclusive
        __syncthreads();
        if (threadIdx.x == 1023) carry += sdata[1023];
        __syncthreads();
    }
}

// scatter edges into CSR slots (int atomics only); fuse norm computation
__global__ void k_build(const float* __restrict__ ew) {
    int e = blockIdx.x * blockDim.x + threadIdx.x;
    if (e < NE) {
        int r = g_row[e];
        int c = g_col[e];
        float nr = g_dis[r] * ew[e] * g_dis[c];
        int slot = atomicAdd(&g_pos[c], 1);
        int idx = g_offs[c] + slot;
        g_src[idx] = r;
        g_nrm[idx] = nr;
    }
}

// ---------------- GEMM: g_h[N,128] = X[N,128] @ W[128,128], optional relu on X ----
// X = Xext if non-null, else g_a1. BM=64, BN=128, BK=16, 128 threads, 8x8 microtile.
template<bool RELU>
__global__ __launch_bounds__(128) void k_gemm(const float* __restrict__ Xext,
                                              const float* __restrict__ W) {
    const float* __restrict__ X = (Xext != nullptr) ? Xext : (const float*)g_a1;

    __shared__ float sX[16][64];    // [k][m] transposed
    __shared__ float sW[16][128];   // [k][n]

    const int tid = threadIdx.x;
    const int ty = tid >> 4;        // 0..7
    const int tx = tid & 15;        // 0..15
    const int bm0 = blockIdx.x * 64;

    float acc[8][8];
#pragma unroll
    for (int i = 0; i < 8; i++)
#pragma unroll
        for (int j = 0; j < 8; j++) acc[i][j] = 0.0f;

    for (int k0 = 0; k0 < DD; k0 += 16) {
#pragma unroll
        for (int t = 0; t < 2; t++) {
            int f = tid * 2 + t;         // 0..255
            int m = f >> 2;
            int kq = f & 3;
            int row = bm0 + m;
            float4 xv = make_float4(0.f, 0.f, 0.f, 0.f);
            if (row < NN) xv = *reinterpret_cast<const float4*>(&X[row * DD + k0 + kq * 4]);
            if (RELU) {
                xv.x = fmaxf(xv.x, 0.f); xv.y = fmaxf(xv.y, 0.f);
                xv.z = fmaxf(xv.z, 0.f); xv.w = fmaxf(xv.w, 0.f);
            }
            sX[kq * 4 + 0][m] = xv.x;
            sX[kq * 4 + 1][m] = xv.y;
            sX[kq * 4 + 2][m] = xv.z;
            sX[kq * 4 + 3][m] = xv.w;
        }
#pragma unroll
        for (int t = 0; t < 4; t++) {
            int f = tid + t * 128;       // 0..511 float4
            int k = f >> 5;
            int n4 = f & 31;
            *reinterpret_cast<float4*>(&sW[k][n4 * 4]) =
                *reinterpret_cast<const float4*>(&W[(k0 + k) * DD + n4 * 4]);
        }
        __syncthreads();

#pragma unroll
        for (int kk = 0; kk < 16; kk++) {
            float4 a0 = *reinterpret_cast<float4*>(&sX[kk][ty * 8]);
            float4 a1 = *reinterpret_cast<float4*>(&sX[kk][ty * 8 + 4]);
            float4 b0 = *reinterpret_cast<float4*>(&sW[kk][tx * 8]);
            float4 b1 = *reinterpret_cast<float4*>(&sW[kk][tx * 8 + 4]);
            float a[8] = {a0.x, a0.y, a0.z, a0.w, a1.x, a1.y, a1.z, a1.w};
            float b[8] = {b0.x, b0.y, b0.z, b0.w, b1.x, b1.y, b1.z, b1.w};
#pragma unroll
            for (int i = 0; i < 8; i++)
#pragma unroll
                for (int j = 0; j < 8; j++) acc[i][j] = fmaf(a[i], b[j], acc[i][j]);
        }
        __syncthreads();
    }

#pragma unroll
    for (int i = 0; i < 8; i++) {
        int row = bm0 + ty * 8 + i;
        if (row < NN) {
#pragma unroll
            for (int j = 0; j < 2; j++) {
                float4 v = make_float4(acc[i][j * 4 + 0], acc[i][j * 4 + 1],
                                       acc[i][j * 4 + 2], acc[i][j * 4 + 3]);
                *reinterpret_cast<float4*>(&g_h[row * DD + tx * 8 + j * 4]) = v;
            }
        }
    }
}

// ---------------- aggregate: warp per node, CSR gather, no atomics ----------------
// out[i,:] = b + dis[i]^2 * g_h[i,:] + sum_j nrm[j] * g_h[src[j],:]
__global__ __launch_bounds__(256) void k_agg(const float* __restrict__ b,
                                             float* __restrict__ outext) {
    float* __restrict__ out = (outext != nullptr) ? outext : (float*)g_a1;
    const float* __restrict__ h = (const float*)g_h;

    int node = blockIdx.x * 8 + (threadIdx.x >> 5);
    int lane = threadIdx.x & 31;
    if (node >= NN) return;

    float s = g_dis[node];
    s = s * s;
    float4 hv = *reinterpret_cast<const float4*>(&h[node * DD + lane * 4]);
    float4 bv = *reinterpret_cast<const float4*>(&b[lane * 4]);
    float ax = bv.x + s * hv.x;
    float ay = bv.y + s * hv.y;
    float az = bv.z + s * hv.z;
    float aw = bv.w + s * hv.w;

    int start = g_offs[node];
    int end   = start + g_cnt[node];

    int j = start;
    for (; j + 1 < end; j += 2) {
        int s0 = g_src[j];
        int s1 = g_src[j + 1];
        float n0 = g_nrm[j];
        float n1 = g_nrm[j + 1];
        float4 v0 = *reinterpret_cast<const float4*>(&h[s0 * DD + lane * 4]);
        float4 v1 = *reinterpret_cast<const float4*>(&h[s1 * DD + lane * 4]);
        ax += n0 * v0.x + n1 * v1.x;
        ay += n0 * v0.y + n1 * v1.y;
        az += n0 * v0.z + n1 * v1.z;
        aw += n0 * v0.w + n1 * v1.w;
    }
    if (j < end) {
        int s0 = g_src[j];
        float n0 = g_nrm[j];
        float4 v0 = *reinterpret_cast<const float4*>(&h[s0 * DD + lane * 4]);
        ax += n0 * v0.x; ay += n0 * v0.y; az += n0 * v0.z; aw += n0 * v0.w;
    }

    *reinterpret_cast<float4*>(&out[node * DD + lane * 4]) = make_float4(ax, ay, az, aw);
}

// ---------------- launch (NO __device__ symbols referenced here) ----------------
extern "C" void kernel_launch(void* const* d_in, const int* in_sizes, int n_in,
                              void* d_out, int out_size) {
    const float* x  = (const float*)d_in[0];
    const void*  ei = d_in[1];                 // [2, E] int32 OR int64
    const float* ew = (const float*)d_in[2];
    const float* W1 = (const float*)d_in[3];
    const float* b1 = (const float*)d_in[4];
    const float* W2 = (const float*)d_in[5];
    const float* b2 = (const float*)d_in[6];
    float* out = (float*)d_out;

    const int T = 256;
    const int gN = (NN + T - 1) / T;
    const int gE = (NE + T - 1) / T;
    const int gG = (NN + 63) / 64;
    const int gA = (NN + 7) / 8;      // 8 warps (nodes) per block

    // ---- index dtype detect + convert ----
    k_detect<<<1, 256>>>(ei);
    k_convert<<<gE, T>>>(ei);

    // ---- prep (shared by both layers) ----
    k_init<<<gN, T>>>();
    k_deg_accum<<<gE, T>>>(ew);
    k_dis<<<gN, T>>>();
    k_scan<<<1, 1024>>>();
    k_build<<<gE, T>>>(ew);

    // ---- layer 1: h = x@W1 ; a1 = aggregate(h) + b1 ----
    k_gemm<false><<<gG, 128>>>(x, W1);
    k_agg<<<gA, T>>>(b1, nullptr);

    // ---- layer 2: h = relu(a1)@W2 ; out = aggregate(h) + b2 ----
    k_gemm<true><<<gG, 128>>>(nullptr, W2);
    k_agg<<<gA, T>>>(b2, out);
}

// round 6
// speedup vs baseline: 1.3033x; 1.3033x over previous
#include <cuda_runtime.h>
#include <cuda_bf16.h>

#define NN 50000
#define NE 800000
#define DD 128
#define SCAN_BS 512
#define NBLK ((NN + SCAN_BS - 1) / SCAN_BS)   // 98

// ---------------- scratch (static __device__; referenced ONLY in device code) ----
__device__ int   g_is64;
__device__ int   g_row[NE];
__device__ int   g_col[NE];
__device__ int   g_cnt[NN];
__device__ int   g_offs[NN + 1];     // CSR offsets + sentinel
__device__ int   g_pos[NN];          // build cursor
__device__ int   g_bsum[NBLK];       // scan block sums
__device__ int   g_src[NE];          // CSR: source per slot
__device__ float g_wcsr[NE];         // CSR: raw edge weight per slot
__device__ float g_dis[NN];          // 1/sqrt(deg)
__device__ float g_h[NN * DD];       // h2 = dis[row]*(X@W)
__device__ float g_a1[NN * DD];      // layer-1 output

// ---------------- dtype detect + convert ----------------
__global__ void k_detect(const void* ei) {
    __shared__ int bad;
    if (threadIdx.x == 0) bad = 0;
    __syncthreads();
    const long long* p = (const long long*)ei;
    for (int i = threadIdx.x; i < 1024; i += blockDim.x) {
        long long v = p[i];
        if (v < 0 || v >= NN) atomicOr(&bad, 1);
    }
    __syncthreads();
    if (threadIdx.x == 0) g_is64 = bad ? 0 : 1;
}

__global__ void k_convert(const void* ei) {
    int e = blockIdx.x * blockDim.x + threadIdx.x;
    if (e < NE) {
        if (g_is64) {
            const long long* p = (const long long*)ei;
            g_row[e] = (int)p[e];
            g_col[e] = (int)p[NE + e];
        } else {
            const int* p = (const int*)ei;
            g_row[e] = p[e];
            g_col[e] = p[NE + e];
        }
    }
}

__global__ void k_init() {
    int i = blockIdx.x * blockDim.x + threadIdx.x;
    if (i < NN) g_cnt[i] = 0;
}

__global__ void k_count() {
    int e = blockIdx.x * blockDim.x + threadIdx.x;
    if (e < NE) atomicAdd(&g_cnt[g_col[e]], 1);
}

// ---------------- hierarchical scan ----------------
__global__ __launch_bounds__(SCAN_BS) void k_scan1() {
    int i = blockIdx.x * SCAN_BS + threadIdx.x;
    int lane = threadIdx.x & 31, wid = threadIdx.x >> 5;
    int v = (i < NN) ? g_cnt[i] : 0;
    int x = v;
#pragma unroll
    for (int o = 1; o < 32; o <<= 1) {
        int t = __shfl_up_sync(0xffffffffu, x, o);
        if (lane >= o) x += t;
    }
    __shared__ int wsum[16];
    if (lane == 31) wsum[wid] = x;
    __syncthreads();
    if (wid == 0) {
        int s = (lane < 16) ? wsum[lane] : 0;
#pragma unroll
        for (int o = 1; o < 16; o <<= 1) {
            int t = __shfl_up_sync(0xffffffffu, s, o);
            if (lane >= o) s += t;
        }
        if (lane < 16) wsum[lane] = s;
    }
    __syncthreads();
    int base = (wid > 0) ? wsum[wid - 1] : 0;
    if (i < NN) g_offs[i] = base + x - v;          // block-local exclusive
    if (threadIdx.x == SCAN_BS - 1) g_bsum[blockIdx.x] = base + x;   // block total
}

__global__ void k_scan2() {
    int t = threadIdx.x;      // 128 threads, NBLK=98 values
    int lane = t & 31, wid = t >> 5;
    int v = (t < NBLK) ? g_bsum[t] : 0;
    int x = v;
#pragma unroll
    for (int o = 1; o < 32; o <<= 1) {
        int tt = __shfl_up_sync(0xffffffffu, x, o);
        if (lane >= o) x += tt;
    }
    __shared__ int wsum[4];
    if (lane == 31) wsum[wid] = x;
    __syncthreads();
    int base = 0;
    for (int w = 0; w < wid; w++) base += wsum[w];
    if (t < NBLK) g_bsum[t] = base + x - v;        // exclusive
}

__global__ __launch_bounds__(SCAN_BS) void k_scan3() {
    int i = blockIdx.x * SCAN_BS + threadIdx.x;
    if (i < NN) {
        int off = g_offs[i] + g_bsum[blockIdx.x];
        g_offs[i] = off;
        g_pos[i] = off;
    }
    if (i == 0) g_offs[NN] = NE;
}

// ---------------- CSR fill (1 int atomic/edge) ----------------
__global__ void k_fill(const float* __restrict__ ew) {
    int e = blockIdx.x * blockDim.x + threadIdx.x;
    if (e < NE) {
        int c = g_col[e];
        int idx = atomicAdd(&g_pos[c], 1);
        g_src[idx] = g_row[e];
        g_wcsr[idx] = ew[e];
    }
}

// ---------------- deg/dis: warp per node, sequential CSR sum, no atomics ------
__global__ __launch_bounds__(256) void k_dis() {
    int node = blockIdx.x * 8 + (threadIdx.x >> 5);
    int lane = threadIdx.x & 31;
    if (node >= NN) return;
    int s0 = g_offs[node], s1 = g_offs[node + 1];
    float sum = 0.0f;
    for (int j = s0 + lane; j < s1; j += 32) sum += g_wcsr[j];
#pragma unroll
    for (int o = 16; o > 0; o >>= 1) sum += __shfl_down_sync(0xffffffffu, sum, o);
    if (lane == 0) g_dis[node] = rsqrtf(1.0f + sum);   // deg >= 1 (self loop)
}

// ---------------- GEMM: g_h[r,:] = dis[r] * (X@W)[r,:], optional relu on X ----
template<bool RELU>
__global__ __launch_bounds__(128) void k_gemm(const float* __restrict__ Xext,
                                              const float* __restrict__ W) {
    const float* __restrict__ X = (Xext != nullptr) ? Xext : (const float*)g_a1;

    __shared__ float sX[16][64];
    __shared__ float sW[16][128];

    const int tid = threadIdx.x;
    const int ty = tid >> 4;
    const int tx = tid & 15;
    const int bm0 = blockIdx.x * 64;

    float acc[8][8];
#pragma unroll
    for (int i = 0; i < 8; i++)
#pragma unroll
        for (int j = 0; j < 8; j++) acc[i][j] = 0.0f;

    for (int k0 = 0; k0 < DD; k0 += 16) {
#pragma unroll
        for (int t = 0; t < 2; t++) {
            int f = tid * 2 + t;
            int m = f >> 2;
            int kq = f & 3;
            int row = bm0 + m;
            float4 xv = make_float4(0.f, 0.f, 0.f, 0.f);
            if (row < NN) xv = *reinterpret_cast<const float4*>(&X[row * DD + k0 + kq * 4]);
            if (RELU) {
                xv.x = fmaxf(xv.x, 0.f); xv.y = fmaxf(xv.y, 0.f);
                xv.z = fmaxf(xv.z, 0.f); xv.w = fmaxf(xv.w, 0.f);
            }
            sX[kq * 4 + 0][m] = xv.x;
            sX[kq * 4 + 1][m] = xv.y;
            sX[kq * 4 + 2][m] = xv.z;
            sX[kq * 4 + 3][m] = xv.w;
        }
#pragma unroll
        for (int t = 0; t < 4; t++) {
            int f = tid + t * 128;
            int k = f >> 5;
            int n4 = f & 31;
            *reinterpret_cast<float4*>(&sW[k][n4 * 4]) =
                *reinterpret_cast<const float4*>(&W[(k0 + k) * DD + n4 * 4]);
        }
        __syncthreads();

#pragma unroll
        for (int kk = 0; kk < 16; kk++) {
            float4 a0 = *reinterpret_cast<float4*>(&sX[kk][ty * 8]);
            float4 a1 = *reinterpret_cast<float4*>(&sX[kk][ty * 8 + 4]);
            float4 b0 = *reinterpret_cast<float4*>(&sW[kk][tx * 8]);
            float4 b1 = *reinterpret_cast<float4*>(&sW[kk][tx * 8 + 4]);
            float a[8] = {a0.x, a0.y, a0.z, a0.w, a1.x, a1.y, a1.z, a1.w};
            float b[8] = {b0.x, b0.y, b0.z, b0.w, b1.x, b1.y, b1.z, b1.w};
#pragma unroll
            for (int i = 0; i < 8; i++)
#pragma unroll
                for (int j = 0; j < 8; j++) acc[i][j] = fmaf(a[i], b[j], acc[i][j]);
        }
        __syncthreads();
    }

#pragma unroll
    for (int i = 0; i < 8; i++) {
        int row = bm0 + ty * 8 + i;
        if (row < NN) {
            float d = g_dis[row];
#pragma unroll
            for (int j = 0; j < 2; j++) {
                float4 v = make_float4(d * acc[i][j * 4 + 0], d * acc[i][j * 4 + 1],
                                       d * acc[i][j * 4 + 2], d * acc[i][j * 4 + 3]);
                *reinterpret_cast<float4*>(&g_h[row * DD + tx * 8 + j * 4]) = v;
            }
        }
    }
}

// ---------------- aggregate: warp per node, CSR gather ----------------
// out[i,:] = b + dis[i]*( h2[i,:] + sum_j ew[j]*h2[src[j],:] )
__global__ __launch_bounds__(256) void k_agg(const float* __restrict__ b,
                                             float* __restrict__ outext) {
    float* __restrict__ out = (outext != nullptr) ? outext : (float*)g_a1;
    const float* __restrict__ h = (const float*)g_h;

    int node = blockIdx.x * 8 + (threadIdx.x >> 5);
    int lane = threadIdx.x & 31;
    if (node >= NN) return;

    float4 hv = *reinterpret_cast<const float4*>(&h[node * DD + lane * 4]);
    float ax = hv.x, ay = hv.y, az = hv.z, aw = hv.w;

    int j = g_offs[node];
    int end = g_offs[node + 1];

    for (; j + 1 < end; j += 2) {
        int s0 = g_src[j];
        int s1 = g_src[j + 1];
        float n0 = g_wcsr[j];
        float n1 = g_wcsr[j + 1];
        float4 v0 = *reinterpret_cast<const float4*>(&h[s0 * DD + lane * 4]);
        float4 v1 = *reinterpret_cast<const float4*>(&h[s1 * DD + lane * 4]);
        ax += n0 * v0.x + n1 * v1.x;
        ay += n0 * v0.y + n1 * v1.y;
        az += n0 * v0.z + n1 * v1.z;
        aw += n0 * v0.w + n1 * v1.w;
    }
    if (j < end) {
        int s0 = g_src[j];
        float n0 = g_wcsr[j];
        float4 v0 = *reinterpret_cast<const float4*>(&h[s0 * DD + lane * 4]);
        ax += n0 * v0.x; ay += n0 * v0.y; az += n0 * v0.z; aw += n0 * v0.w;
    }

    float s = g_dis[node];
    float4 bv = *reinterpret_cast<const float4*>(&b[lane * 4]);
    *reinterpret_cast<float4*>(&out[node * DD + lane * 4]) =
        make_float4(bv.x + s * ax, bv.y + s * ay, bv.z + s * az, bv.w + s * aw);
}

// ---------------- launch (NO __device__ symbols referenced here) ----------------
extern "C" void kernel_launch(void* const* d_in, const int* in_sizes, int n_in,
                              void* d_out, int out_size) {
    const float* x  = (const float*)d_in[0];
    const void*  ei = d_in[1];
    const float* ew = (const float*)d_in[2];
    const float* W1 = (const float*)d_in[3];
    const float* b1 = (const float*)d_in[4];
    const float* W2 = (const float*)d_in[5];
    const float* b2 = (const float*)d_in[6];
    float* out = (float*)d_out;

    const int T = 256;
    const int gN = (NN + T - 1) / T;
    const int gE = (NE + T - 1) / T;
    const int gG = (NN + 63) / 64;
    const int gA = (NN + 7) / 8;

    k_detect<<<1, 256>>>(ei);
    k_convert<<<gE, T>>>(ei);
    k_init<<<gN, T>>>();
    k_count<<<gE, T>>>();
    k_scan1<<<NBLK, SCAN_BS>>>();
    k_scan2<<<1, 128>>>();
    k_scan3<<<NBLK, SCAN_BS>>>();
    k_fill<<<gE, T>>>(ew);
    k_dis<<<gA, T>>>();

    k_gemm<false><<<gG, 128>>>(x, W1);
    k_agg<<<gA, T>>>(b1, nullptr);

    k_gemm<true><<<gG, 128>>>(nullptr, W2);
    k_agg<<<gA, T>>>(b2, out);
}

// round 7
// speedup vs baseline: 1.4943x; 1.1466x over previous
#include <cuda_runtime.h>
#include <cuda_bf16.h>

#define NN 50000
#define NE 800000
#define DD 128
#define SCAN_BS 512
#define NBLK ((NN + SCAN_BS - 1) / SCAN_BS)   // 98

// ---------------- scratch (static __device__; referenced ONLY in device code) ----
__device__ int   g_is64;
__device__ int   g_row[NE];
__device__ int   g_col[NE];
__device__ int   g_cnt[NN];
__device__ int   g_offs[NN + 1];
__device__ int   g_pos[NN];
__device__ int   g_bsum[NBLK];
__device__ int   g_src[NE];
__device__ float g_wcsr[NE];
__device__ float g_dis[NN];
__device__ float g_h[NN * DD];
__device__ float g_a1[NN * DD];

// ---------------- dtype detect + convert ----------------
__global__ void k_detect(const void* ei) {
    __shared__ int bad;
    if (threadIdx.x == 0) bad = 0;
    __syncthreads();
    const long long* p = (const long long*)ei;
    for (int i = threadIdx.x; i < 1024; i += blockDim.x) {
        long long v = p[i];
        if (v < 0 || v >= NN) atomicOr(&bad, 1);
    }
    __syncthreads();
    if (threadIdx.x == 0) g_is64 = bad ? 0 : 1;
}

__global__ void k_convert(const void* ei) {
    int e = blockIdx.x * blockDim.x + threadIdx.x;
    if (e < NE) {
        if (g_is64) {
            const long long* p = (const long long*)ei;
            g_row[e] = (int)p[e];
            g_col[e] = (int)p[NE + e];
        } else {
            const int* p = (const int*)ei;
            g_row[e] = p[e];
            g_col[e] = p[NE + e];
        }
    }
}

__global__ void k_init() {
    int i = blockIdx.x * blockDim.x + threadIdx.x;
    if (i < NN) g_cnt[i] = 0;
}

__global__ void k_count() {
    int e = blockIdx.x * blockDim.x + threadIdx.x;
    if (e < NE) atomicAdd(&g_cnt[g_col[e]], 1);
}

// ---------------- hierarchical scan ----------------
__global__ __launch_bounds__(SCAN_BS) void k_scan1() {
    int i = blockIdx.x * SCAN_BS + threadIdx.x;
    int lane = threadIdx.x & 31, wid = threadIdx.x >> 5;
    int v = (i < NN) ? g_cnt[i] : 0;
    int x = v;
#pragma unroll
    for (int o = 1; o < 32; o <<= 1) {
        int t = __shfl_up_sync(0xffffffffu, x, o);
        if (lane >= o) x += t;
    }
    __shared__ int wsum[16];
    if (lane == 31) wsum[wid] = x;
    __syncthreads();
    if (wid == 0) {
        int s = (lane < 16) ? wsum[lane] : 0;
#pragma unroll
        for (int o = 1; o < 16; o <<= 1) {
            int t = __shfl_up_sync(0xffffffffu, s, o);
            if (lane >= o) s += t;
        }
        if (lane < 16) wsum[lane] = s;
    }
    __syncthreads();
    int base = (wid > 0) ? wsum[wid - 1] : 0;
    if (i < NN) g_offs[i] = base + x - v;
    if (threadIdx.x == SCAN_BS - 1) g_bsum[blockIdx.x] = base + x;
}

__global__ void k_scan2() {
    int t = threadIdx.x;
    int lane = t & 31, wid = t >> 5;
    int v = (t < NBLK) ? g_bsum[t] : 0;
    int x = v;
#pragma unroll
    for (int o = 1; o < 32; o <<= 1) {
        int tt = __shfl_up_sync(0xffffffffu, x, o);
        if (lane >= o) x += tt;
    }
    __shared__ int wsum[4];
    if (lane == 31) wsum[wid] = x;
    __syncthreads();
    int base = 0;
    for (int w = 0; w < wid; w++) base += wsum[w];
    if (t < NBLK) g_bsum[t] = base + x - v;
}

__global__ __launch_bounds__(SCAN_BS) void k_scan3() {
    int i = blockIdx.x * SCAN_BS + threadIdx.x;
    if (i < NN) {
        int off = g_offs[i] + g_bsum[blockIdx.x];
        g_offs[i] = off;
        g_pos[i] = off;
    }
    if (i == 0) g_offs[NN] = NE;
}

// ---------------- CSR fill ----------------
__global__ void k_fill(const float* __restrict__ ew) {
    int e = blockIdx.x * blockDim.x + threadIdx.x;
    if (e < NE) {
        int c = g_col[e];
        int idx = atomicAdd(&g_pos[c], 1);
        g_src[idx] = g_row[e];
        g_wcsr[idx] = ew[e];
    }
}

// ---------------- deg/dis ----------------
__global__ __launch_bounds__(256) void k_dis() {
    int node = blockIdx.x * 8 + (threadIdx.x >> 5);
    int lane = threadIdx.x & 31;
    if (node >= NN) return;
    int s0 = g_offs[node], s1 = g_offs[node + 1];
    float sum = 0.0f;
    for (int j = s0 + lane; j < s1; j += 32) sum += g_wcsr[j];
#pragma unroll
    for (int o = 16; o > 0; o >>= 1) sum += __shfl_down_sync(0xffffffffu, sum, o);
    if (lane == 0) g_dis[node] = rsqrtf(1.0f + sum);
}

// ---------------- tf32 helpers ----------------
__device__ __forceinline__ void split_tf32(float v, float& hi, float& lo) {
    unsigned uh;
    asm("cvt.rna.tf32.f32 %0, %1;" : "=r"(uh) : "f"(v));
    hi = __uint_as_float(uh);
    float r = v - hi;
    unsigned ul;
    asm("cvt.rna.tf32.f32 %0, %1;" : "=r"(ul) : "f"(r));
    lo = __uint_as_float(ul);
}

__device__ __forceinline__ void mma_tf32(float* d, const unsigned* a, const unsigned* b) {
    asm volatile("mma.sync.aligned.m16n8k8.row.col.f32.tf32.tf32.f32 "
                 "{%0,%1,%2,%3}, {%4,%5,%6,%7}, {%8,%9}, {%0,%1,%2,%3};"
                 : "+f"(d[0]), "+f"(d[1]), "+f"(d[2]), "+f"(d[3])
                 : "r"(a[0]), "r"(a[1]), "r"(a[2]), "r"(a[3]), "r"(b[0]), "r"(b[1]));
}

// ---------------- GEMM (tensor core, tf32 split): g_h[r,:] = dis[r]*(X@W)[r,:] ----
// BM=128, BN=128, K chunks of 32. 256 threads = 8 warps (4 m x 2 n).
// Each warp: 32 rows x 64 cols = 2 mtiles x 8 ntiles of m16n8.
template<bool RELU>
__global__ __launch_bounds__(256) void k_gemm(const float* __restrict__ Xext,
                                              const float* __restrict__ W) {
    const float* __restrict__ X = (Xext != nullptr) ? Xext : (const float*)g_a1;

    __shared__ float sXh[128][36], sXl[128][36];   // stride 36: conflict-free frags
    __shared__ float sWh[32][136], sWl[32][136];   // stride 136: conflict-free frags

    const int tid = threadIdx.x;
    const int wid = tid >> 5, lane = tid & 31;
    const int g = lane >> 2, tig = lane & 3;
    const int warp_m = wid & 3, warp_n = wid >> 2;
    const int bm0 = blockIdx.x * 128;

    float acc[2][8][4];
#pragma unroll
    for (int mt = 0; mt < 2; mt++)
#pragma unroll
        for (int nt = 0; nt < 8; nt++)
#pragma unroll
            for (int c = 0; c < 4; c++) acc[mt][nt][c] = 0.0f;

    for (int k0 = 0; k0 < DD; k0 += 32) {
        // stage X chunk [128 rows][32 k] as hi/lo planes
#pragma unroll
        for (int i = 0; i < 4; i++) {
            int f = tid + i * 256;       // 0..1023 float4 slots
            int r = f >> 3, c4 = f & 7;
            int row = bm0 + r;
            float4 v = make_float4(0.f, 0.f, 0.f, 0.f);
            if (row < NN) v = *reinterpret_cast<const float4*>(&X[row * DD + k0 + c4 * 4]);
            if (RELU) {
                v.x = fmaxf(v.x, 0.f); v.y = fmaxf(v.y, 0.f);
                v.z = fmaxf(v.z, 0.f); v.w = fmaxf(v.w, 0.f);
            }
            float h0, l0, h1, l1, h2, l2, h3, l3;
            split_tf32(v.x, h0, l0); split_tf32(v.y, h1, l1);
            split_tf32(v.z, h2, l2); split_tf32(v.w, h3, l3);
            int c = c4 * 4;
            sXh[r][c] = h0; sXh[r][c + 1] = h1; sXh[r][c + 2] = h2; sXh[r][c + 3] = h3;
            sXl[r][c] = l0; sXl[r][c + 1] = l1; sXl[r][c + 2] = l2; sXl[r][c + 3] = l3;
        }
        // stage W chunk [32 k][128 n]
#pragma unroll
        for (int i = 0; i < 4; i++) {
            int f = tid + i * 256;       // 0..1023 float4 slots
            int k = f >> 5, c4 = f & 31;
            float4 v = *reinterpret_cast<const float4*>(&W[(k0 + k) * DD + c4 * 4]);
            float h0, l0, h1, l1, h2, l2, h3, l3;
            split_tf32(v.x, h0, l0); split_tf32(v.y, h1, l1);
            split_tf32(v.z, h2, l2); split_tf32(v.w, h3, l3);
            int c = c4 * 4;
            sWh[k][c] = h0; sWh[k][c + 1] = h1; sWh[k][c + 2] = h2; sWh[k][c + 3] = h3;
            sWl[k][c] = l0; sWl[k][c + 1] = l1; sWl[k][c + 2] = l2; sWl[k][c + 3] = l3;
        }
        __syncthreads();

#pragma unroll
        for (int kk = 0; kk < 32; kk += 8) {
            unsigned Ah[2][4], Al[2][4], Bh[8][2], Bl[8][2];
#pragma unroll
            for (int mt = 0; mt < 2; mt++) {
                int r0 = warp_m * 32 + mt * 16 + g;
                Ah[mt][0] = __float_as_uint(sXh[r0][kk + tig]);
                Ah[mt][1] = __float_as_uint(sXh[r0 + 8][kk + tig]);
                Ah[mt][2] = __float_as_uint(sXh[r0][kk + tig + 4]);
                Ah[mt][3] = __float_as_uint(sXh[r0 + 8][kk + tig + 4]);
                Al[mt][0] = __float_as_uint(sXl[r0][kk + tig]);
                Al[mt][1] = __float_as_uint(sXl[r0 + 8][kk + tig]);
                Al[mt][2] = __float_as_uint(sXl[r0][kk + tig + 4]);
                Al[mt][3] = __float_as_uint(sXl[r0 + 8][kk + tig + 4]);
            }
#pragma unroll
            for (int nt = 0; nt < 8; nt++) {
                int n = warp_n * 64 + nt * 8 + g;
                Bh[nt][0] = __float_as_uint(sWh[kk + tig][n]);
                Bh[nt][1] = __float_as_uint(sWh[kk + tig + 4][n]);
                Bl[nt][0] = __float_as_uint(sWl[kk + tig][n]);
                Bl[nt][1] = __float_as_uint(sWl[kk + tig + 4][n]);
            }
#pragma unroll
            for (int mt = 0; mt < 2; mt++)
#pragma unroll
                for (int nt = 0; nt < 8; nt++) {
                    mma_tf32(acc[mt][nt], Ah[mt], Bh[nt]);
                    mma_tf32(acc[mt][nt], Ah[mt], Bl[nt]);
                    mma_tf32(acc[mt][nt], Al[mt], Bh[nt]);
                }
        }
        __syncthreads();
    }

    // epilogue: scale by dis[row], write g_h
#pragma unroll
    for (int mt = 0; mt < 2; mt++) {
        int r0 = bm0 + warp_m * 32 + mt * 16 + g;
        int r1 = r0 + 8;
        float d0 = (r0 < NN) ? g_dis[r0] : 0.0f;
        float d1 = (r1 < NN) ? g_dis[r1] : 0.0f;
#pragma unroll
        for (int nt = 0; nt < 8; nt++) {
            int col = warp_n * 64 + nt * 8 + tig * 2;
            if (r0 < NN)
                *reinterpret_cast<float2*>(&g_h[r0 * DD + col]) =
                    make_float2(d0 * acc[mt][nt][0], d0 * acc[mt][nt][1]);
            if (r1 < NN)
                *reinterpret_cast<float2*>(&g_h[r1 * DD + col]) =
                    make_float2(d1 * acc[mt][nt][2], d1 * acc[mt][nt][3]);
        }
    }
}

// ---------------- aggregate: warp per node, CSR gather ----------------
__global__ __launch_bounds__(256) void k_agg(const float* __restrict__ b,
                                             float* __restrict__ outext) {
    float* __restrict__ out = (outext != nullptr) ? outext : (float*)g_a1;
    const float* __restrict__ h = (const float*)g_h;

    int node = blockIdx.x * 8 + (threadIdx.x >> 5);
    int lane = threadIdx.x & 31;
    if (node >= NN) return;

    float4 hv = *reinterpret_cast<const float4*>(&h[node * DD + lane * 4]);
    float ax = hv.x, ay = hv.y, az = hv.z, aw = hv.w;

    int j = g_offs[node];
    int end = g_offs[node + 1];

    for (; j + 1 < end; j += 2) {
        int s0 = g_src[j];
        int s1 = g_src[j + 1];
        float n0 = g_wcsr[j];
        float n1 = g_wcsr[j + 1];
        float4 v0 = *reinterpret_cast<const float4*>(&h[s0 * DD + lane * 4]);
        float4 v1 = *reinterpret_cast<const float4*>(&h[s1 * DD + lane * 4]);
        ax += n0 * v0.x + n1 * v1.x;
        ay += n0 * v0.y + n1 * v1.y;
        az += n0 * v0.z + n1 * v1.z;
        aw += n0 * v0.w + n1 * v1.w;
    }
    if (j < end) {
        int s0 = g_src[j];
        float n0 = g_wcsr[j];
        float4 v0 = *reinterpret_cast<const float4*>(&h[s0 * DD + lane * 4]);
        ax += n0 * v0.x; ay += n0 * v0.y; az += n0 * v0.z; aw += n0 * v0.w;
    }

    float s = g_dis[node];
    float4 bv = *reinterpret_cast<const float4*>(&b[lane * 4]);
    *reinterpret_cast<float4*>(&out[node * DD + lane * 4]) =
        make_float4(bv.x + s * ax, bv.y + s * ay, bv.z + s * az, bv.w + s * aw);
}

// ---------------- launch ----------------
extern "C" void kernel_launch(void* const* d_in, const int* in_sizes, int n_in,
                              void* d_out, int out_size) {
    const float* x  = (const float*)d_in[0];
    const void*  ei = d_in[1];
    const float* ew = (const float*)d_in[2];
    const float* W1 = (const float*)d_in[3];
    const float* b1 = (const float*)d_in[4];
    const float* W2 = (const float*)d_in[5];
    const float* b2 = (const float*)d_in[6];
    float* out = (float*)d_out;

    const int T = 256;
    const int gN = (NN + T - 1) / T;
    const int gE = (NE + T - 1) / T;
    const int gG = (NN + 127) / 128;
    const int gA = (NN + 7) / 8;

    k_detect<<<1, 256>>>(ei);
    k_convert<<<gE, T>>>(ei);
    k_init<<<gN, T>>>();
    k_count<<<gE, T>>>();
    k_scan1<<<NBLK, SCAN_BS>>>();
    k_scan2<<<1, 128>>>();
    k_scan3<<<NBLK, SCAN_BS>>>();
    k_fill<<<gE, T>>>(ew);
    k_dis<<<gA, T>>>();

    k_gemm<false><<<gG, 256>>>(x, W1);
    k_agg<<<gA, T>>>(b1, nullptr);

    k_gemm<true><<<gG, 256>>>(nullptr, W2);
    k_agg<<<gA, T>>>(b2, out);
}

// round 8
// speedup vs baseline: 1.5242x; 1.0200x over previous
#include <cuda_runtime.h>
#include <cuda_bf16.h>

#define NN 50000
#define NE 800000
#define DD 128
#define SCAN_BS 512
#define NBLK ((NN + SCAN_BS - 1) / SCAN_BS)   // 98

// ---------------- scratch (static __device__; referenced ONLY in device code) ----
__device__ int   g_is64;
__device__ int   g_cnt[NN];
__device__ int   g_offs[NN + 1];
__device__ int   g_pos[NN];
__device__ int   g_bsum[NBLK];
__device__ int   g_src[NE];
__device__ float g_wcsr[NE];
__device__ float g_dis[NN];
__device__ float g_h[NN * DD];
__device__ float g_a1[NN * DD];

// ---------------- dtype detect ----------------
__global__ void k_detect(const void* ei) {
    __shared__ int bad;
    if (threadIdx.x == 0) bad = 0;
    __syncthreads();
    const long long* p = (const long long*)ei;
    for (int i = threadIdx.x; i < 1024; i += blockDim.x) {
        long long v = p[i];
        if (v < 0 || v >= NN) atomicOr(&bad, 1);
    }
    __syncthreads();
    if (threadIdx.x == 0) g_is64 = bad ? 0 : 1;
}

__global__ void k_init() {
    int i = blockIdx.x * blockDim.x + threadIdx.x;
    if (i < NN) g_cnt[i] = 0;
}

// count incoming edges, reading edge_index directly
__global__ void k_count(const void* ei) {
    int e = blockIdx.x * blockDim.x + threadIdx.x;
    if (e < NE) {
        int c = g_is64 ? (int)((const long long*)ei)[NE + e]
                       : ((const int*)ei)[NE + e];
        atomicAdd(&g_cnt[c], 1);
    }
}

// ---------------- hierarchical scan ----------------
__global__ __launch_bounds__(SCAN_BS) void k_scan1() {
    int i = blockIdx.x * SCAN_BS + threadIdx.x;
    int lane = threadIdx.x & 31, wid = threadIdx.x >> 5;
    int v = (i < NN) ? g_cnt[i] : 0;
    int x = v;
#pragma unroll
    for (int o = 1; o < 32; o <<= 1) {
        int t = __shfl_up_sync(0xffffffffu, x, o);
        if (lane >= o) x += t;
    }
    __shared__ int wsum[16];
    if (lane == 31) wsum[wid] = x;
    __syncthreads();
    if (wid == 0) {
        int s = (lane < 16) ? wsum[lane] : 0;
#pragma unroll
        for (int o = 1; o < 16; o <<= 1) {
            int t = __shfl_up_sync(0xffffffffu, s, o);
            if (lane >= o) s += t;
        }
        if (lane < 16) wsum[lane] = s;
    }
    __syncthreads();
    int base = (wid > 0) ? wsum[wid - 1] : 0;
    if (i < NN) g_offs[i] = base + x - v;
    if (threadIdx.x == SCAN_BS - 1) g_bsum[blockIdx.x] = base + x;
}

__global__ void k_scan2() {
    int t = threadIdx.x;
    int lane = t & 31, wid = t >> 5;
    int v = (t < NBLK) ? g_bsum[t] : 0;
    int x = v;
#pragma unroll
    for (int o = 1; o < 32; o <<= 1) {
        int tt = __shfl_up_sync(0xffffffffu, x, o);
        if (lane >= o) x += tt;
    }
    __shared__ int wsum[4];
    if (lane == 31) wsum[wid] = x;
    __syncthreads();
    int base = 0;
    for (int w = 0; w < wid; w++) base += wsum[w];
    if (t < NBLK) g_bsum[t] = base + x - v;
}

__global__ __launch_bounds__(SCAN_BS) void k_scan3() {
    int i = blockIdx.x * SCAN_BS + threadIdx.x;
    if (i < NN) {
        int off = g_offs[i] + g_bsum[blockIdx.x];
        g_offs[i] = off;
        g_pos[i] = off;
    }
    if (i == 0) g_offs[NN] = NE;
}

// ---------------- CSR fill (direct edge_index read) ----------------
__global__ void k_fill(const void* ei, const float* __restrict__ ew) {
    int e = blockIdx.x * blockDim.x + threadIdx.x;
    if (e < NE) {
        int r, c;
        if (g_is64) {
            const long long* p = (const long long*)ei;
            r = (int)p[e];
            c = (int)p[NE + e];
        } else {
            const int* p = (const int*)ei;
            r = p[e];
            c = p[NE + e];
        }
        int idx = atomicAdd(&g_pos[c], 1);
        g_src[idx] = r;
        g_wcsr[idx] = ew[e];
    }
}

// ---------------- deg/dis ----------------
__global__ __launch_bounds__(256) void k_dis() {
    int node = blockIdx.x * 8 + (threadIdx.x >> 5);
    int lane = threadIdx.x & 31;
    if (node >= NN) return;
    int s0 = g_offs[node], s1 = g_offs[node + 1];
    float sum = 0.0f;
    for (int j = s0 + lane; j < s1; j += 32) sum += g_wcsr[j];
#pragma unroll
    for (int o = 16; o > 0; o >>= 1) sum += __shfl_down_sync(0xffffffffu, sum, o);
    if (lane == 0) g_dis[node] = rsqrtf(1.0f + sum);
}

// ---------------- tf32 helpers ----------------
__device__ __forceinline__ void split_tf32(float v, float& hi, float& lo) {
    unsigned uh;
    asm("cvt.rna.tf32.f32 %0, %1;" : "=r"(uh) : "f"(v));
    hi = __uint_as_float(uh);
    float r = v - hi;
    unsigned ul;
    asm("cvt.rna.tf32.f32 %0, %1;" : "=r"(ul) : "f"(r));
    lo = __uint_as_float(ul);
}

__device__ __forceinline__ void mma_tf32(float* d, const unsigned* a, const unsigned* b) {
    asm volatile("mma.sync.aligned.m16n8k8.row.col.f32.tf32.tf32.f32 "
                 "{%0,%1,%2,%3}, {%4,%5,%6,%7}, {%8,%9}, {%0,%1,%2,%3};"
                 : "+f"(d[0]), "+f"(d[1]), "+f"(d[2]), "+f"(d[3])
                 : "r"(a[0]), "r"(a[1]), "r"(a[2]), "r"(a[3]), "r"(b[0]), "r"(b[1]));
}

// ---------------- GEMM (tensor core, tf32 split): g_h[r,:] = dis[r]*(X@W)[r,:] ----
template<bool RELU>
__global__ __launch_bounds__(256) void k_gemm(const float* __restrict__ Xext,
                                              const float* __restrict__ W) {
    const float* __restrict__ X = (Xext != nullptr) ? Xext : (const float*)g_a1;

    __shared__ float sXh[128][36], sXl[128][36];
    __shared__ float sWh[32][136], sWl[32][136];

    const int tid = threadIdx.x;
    const int wid = tid >> 5, lane = tid & 31;
    const int g = lane >> 2, tig = lane & 3;
    const int warp_m = wid & 3, warp_n = wid >> 2;
    const int bm0 = blockIdx.x * 128;

    float acc[2][8][4];
#pragma unroll
    for (int mt = 0; mt < 2; mt++)
#pragma unroll
        for (int nt = 0; nt < 8; nt++)
#pragma unroll
            for (int c = 0; c < 4; c++) acc[mt][nt][c] = 0.0f;

    for (int k0 = 0; k0 < DD; k0 += 32) {
#pragma unroll
        for (int i = 0; i < 4; i++) {
            int f = tid + i * 256;
            int r = f >> 3, c4 = f & 7;
            int row = bm0 + r;
            float4 v = make_float4(0.f, 0.f, 0.f, 0.f);
            if (row < NN) v = *reinterpret_cast<const float4*>(&X[row * DD + k0 + c4 * 4]);
            if (RELU) {
                v.x = fmaxf(v.x, 0.f); v.y = fmaxf(v.y, 0.f);
                v.z = fmaxf(v.z, 0.f); v.w = fmaxf(v.w, 0.f);
            }
            float h0, l0, h1, l1, h2, l2, h3, l3;
            split_tf32(v.x, h0, l0); split_tf32(v.y, h1, l1);
            split_tf32(v.z, h2, l2); split_tf32(v.w, h3, l3);
            int c = c4 * 4;
            sXh[r][c] = h0; sXh[r][c + 1] = h1; sXh[r][c + 2] = h2; sXh[r][c + 3] = h3;
            sXl[r][c] = l0; sXl[r][c + 1] = l1; sXl[r][c + 2] = l2; sXl[r][c + 3] = l3;
        }
#pragma unroll
        for (int i = 0; i < 4; i++) {
            int f = tid + i * 256;
            int k = f >> 5, c4 = f & 31;
            float4 v = *reinterpret_cast<const float4*>(&W[(k0 + k) * DD + c4 * 4]);
            float h0, l0, h1, l1, h2, l2, h3, l3;
            split_tf32(v.x, h0, l0); split_tf32(v.y, h1, l1);
            split_tf32(v.z, h2, l2); split_tf32(v.w, h3, l3);
            int c = c4 * 4;
            sWh[k][c] = h0; sWh[k][c + 1] = h1; sWh[k][c + 2] = h2; sWh[k][c + 3] = h3;
            sWl[k][c] = l0; sWl[k][c + 1] = l1; sWl[k][c + 2] = l2; sWl[k][c + 3] = l3;
        }
        __syncthreads();

#pragma unroll
        for (int kk = 0; kk < 32; kk += 8) {
            unsigned Ah[2][4], Al[2][4], Bh[8][2], Bl[8][2];
#pragma unroll
            for (int mt = 0; mt < 2; mt++) {
                int r0 = warp_m * 32 + mt * 16 + g;
                Ah[mt][0] = __float_as_uint(sXh[r0][kk + tig]);
                Ah[mt][1] = __float_as_uint(sXh[r0 + 8][kk + tig]);
                Ah[mt][2] = __float_as_uint(sXh[r0][kk + tig + 4]);
                Ah[mt][3] = __float_as_uint(sXh[r0 + 8][kk + tig + 4]);
                Al[mt][0] = __float_as_uint(sXl[r0][kk + tig]);
                Al[mt][1] = __float_as_uint(sXl[r0 + 8][kk + tig]);
                Al[mt][2] = __float_as_uint(sXl[r0][kk + tig + 4]);
                Al[mt][3] = __float_as_uint(sXl[r0 + 8][kk + tig + 4]);
            }
#pragma unroll
            for (int nt = 0; nt < 8; nt++) {
                int n = warp_n * 64 + nt * 8 + g;
                Bh[nt][0] = __float_as_uint(sWh[kk + tig][n]);
                Bh[nt][1] = __float_as_uint(sWh[kk + tig + 4][n]);
                Bl[nt][0] = __float_as_uint(sWl[kk + tig][n]);
                Bl[nt][1] = __float_as_uint(sWl[kk + tig + 4][n]);
            }
#pragma unroll
            for (int mt = 0; mt < 2; mt++)
#pragma unroll
                for (int nt = 0; nt < 8; nt++) {
                    mma_tf32(acc[mt][nt], Ah[mt], Bh[nt]);
                    mma_tf32(acc[mt][nt], Ah[mt], Bl[nt]);
                    mma_tf32(acc[mt][nt], Al[mt], Bh[nt]);
                }
        }
        __syncthreads();
    }

#pragma unroll
    for (int mt = 0; mt < 2; mt++) {
        int r0 = bm0 + warp_m * 32 + mt * 16 + g;
        int r1 = r0 + 8;
        float d0 = (r0 < NN) ? g_dis[r0] : 0.0f;
        float d1 = (r1 < NN) ? g_dis[r1] : 0.0f;
#pragma unroll
        for (int nt = 0; nt < 8; nt++) {
            int col = warp_n * 64 + nt * 8 + tig * 2;
            if (r0 < NN)
                *reinterpret_cast<float2*>(&g_h[r0 * DD + col]) =
                    make_float2(d0 * acc[mt][nt][0], d0 * acc[mt][nt][1]);
            if (r1 < NN)
                *reinterpret_cast<float2*>(&g_h[r1 * DD + col]) =
                    make_float2(d1 * acc[mt][nt][2], d1 * acc[mt][nt][3]);
        }
    }
}

// ---------------- aggregate: warp per node, CSR gather, 4-way unrolled --------
__global__ __launch_bounds__(256) void k_agg(const float* __restrict__ b,
                                             float* __restrict__ outext) {
    float* __restrict__ out = (outext != nullptr) ? outext : (float*)g_a1;
    const float* __restrict__ h = (const float*)g_h;

    int node = blockIdx.x * 8 + (threadIdx.x >> 5);
    int lane = threadIdx.x & 31;
    if (node >= NN) return;

    float4 hv = *reinterpret_cast<const float4*>(&h[node * DD + lane * 4]);
    float ax = hv.x, ay = hv.y, az = hv.z, aw = hv.w;

    int j = g_offs[node];
    int end = g_offs[node + 1];

    for (; j + 3 < end; j += 4) {
        int s0 = g_src[j],     s1 = g_src[j + 1];
        int s2 = g_src[j + 2], s3 = g_src[j + 3];
        float n0 = g_wcsr[j],     n1 = g_wcsr[j + 1];
        float n2 = g_wcsr[j + 2], n3 = g_wcsr[j + 3];
        float4 v0 = *reinterpret_cast<const float4*>(&h[s0 * DD + lane * 4]);
        float4 v1 = *reinterpret_cast<const float4*>(&h[s1 * DD + lane * 4]);
        float4 v2 = *reinterpret_cast<const float4*>(&h[s2 * DD + lane * 4]);
        float4 v3 = *reinterpret_cast<const float4*>(&h[s3 * DD + lane * 4]);
        ax += n0 * v0.x + n1 * v1.x + n2 * v2.x + n3 * v3.x;
        ay += n0 * v0.y + n1 * v1.y + n2 * v2.y + n3 * v3.y;
        az += n0 * v0.z + n1 * v1.z + n2 * v2.z + n3 * v3.z;
        aw += n0 * v0.w + n1 * v1.w + n2 * v2.w + n3 * v3.w;
    }
    for (; j < end; j++) {
        int s0 = g_src[j];
        float n0 = g_wcsr[j];
        float4 v0 = *reinterpret_cast<const float4*>(&h[s0 * DD + lane * 4]);
        ax += n0 * v0.x; ay += n0 * v0.y; az += n0 * v0.z; aw += n0 * v0.w;
    }

    float s = g_dis[node];
    float4 bv = *reinterpret_cast<const float4*>(&b[lane * 4]);
    *reinterpret_cast<float4*>(&out[node * DD + lane * 4]) =
        make_float4(bv.x + s * ax, bv.y + s * ay, bv.z + s * az, bv.w + s * aw);
}

// ---------------- launch ----------------
extern "C" void kernel_launch(void* const* d_in, const int* in_sizes, int n_in,
                              void* d_out, int out_size) {
    const float* x  = (const float*)d_in[0];
    const void*  ei = d_in[1];
    const float* ew = (const float*)d_in[2];
    const float* W1 = (const float*)d_in[3];
    const float* b1 = (const float*)d_in[4];
    const float* W2 = (const float*)d_in[5];
    const float* b2 = (const float*)d_in[6];
    float* out = (float*)d_out;

    const int T = 256;
    const int gN = (NN + T - 1) / T;
    const int gE = (NE + T - 1) / T;
    const int gG = (NN + 127) / 128;
    const int gA = (NN + 7) / 8;

    k_detect<<<1, 256>>>(ei);
    k_init<<<gN, T>>>();
    k_count<<<gE, T>>>(ei);
    k_scan1<<<NBLK, SCAN_BS>>>();
    k_scan2<<<1, 128>>>();
    k_scan3<<<NBLK, SCAN_BS>>>();
    k_fill<<<gE, T>>>(ei, ew);
    k_dis<<<gA, T>>>();

    k_gemm<false><<<gG, 256>>>(x, W1);
    k_agg<<<gA, T>>>(b1, nullptr);

    k_gemm<true><<<gG, 256>>>(nullptr, W2);
    k_agg<<<gA, T>>>(b2, out);
}

// round 9
// speedup vs baseline: 1.6264x; 1.0671x over previous
#include <cuda_runtime.h>
#include <cuda_bf16.h>

#define NN 50000
#define NE 800000
#define DD 128
#define SCAN_BS 512
#define NBLK ((NN + SCAN_BS - 1) / SCAN_BS)   // 98

// ---------------- scratch (static __device__; referenced ONLY in device code) ----
__device__ int   g_is64;
__device__ int   g_cnt[NN];
__device__ float g_deg[NN];
__device__ int   g_offs[NN + 1];
__device__ int   g_pos[NN];
__device__ int   g_bsum[NBLK];
__device__ int   g_src[NE];
__device__ float g_wcsr[NE];         // full GCN norm per CSR slot
__device__ float g_dis[NN];
__device__ float g_h[NN * DD];       // raw X@W
__device__ float g_a1[NN * DD];
__device__ float g_Wh[2][DD * 136];  // pre-split tf32 hi planes (W1, W2)
__device__ float g_Wl[2][DD * 136];  // pre-split tf32 lo planes

// ---------------- prep0: detect dtype + zero cnt/deg ----------------
__global__ void k_prep0(const void* ei) {
    int i = blockIdx.x * blockDim.x + threadIdx.x;
    if (i < NN) { g_cnt[i] = 0; g_deg[i] = 0.0f; }
    if (blockIdx.x == 0) {
        __shared__ int bad;
        if (threadIdx.x == 0) bad = 0;
        __syncthreads();
        const long long* p = (const long long*)ei;
        for (int t = threadIdx.x; t < 1024; t += blockDim.x) {
            long long v = p[t];
            if (v < 0 || v >= NN) atomicOr(&bad, 1);
        }
        __syncthreads();
        if (threadIdx.x == 0) g_is64 = bad ? 0 : 1;
    }
}

// ---------------- count + weighted degree ----------------
__global__ void k_count(const void* ei, const float* __restrict__ ew) {
    int e = blockIdx.x * blockDim.x + threadIdx.x;
    if (e < NE) {
        int c = g_is64 ? (int)((const long long*)ei)[NE + e]
                       : ((const int*)ei)[NE + e];
        atomicAdd(&g_cnt[c], 1);
        atomicAdd(&g_deg[c], ew[e]);
    }
}

// ---------------- hierarchical scan ----------------
__global__ __launch_bounds__(SCAN_BS) void k_scan1() {
    int i = blockIdx.x * SCAN_BS + threadIdx.x;
    int lane = threadIdx.x & 31, wid = threadIdx.x >> 5;
    int v = (i < NN) ? g_cnt[i] : 0;
    int x = v;
#pragma unroll
    for (int o = 1; o < 32; o <<= 1) {
        int t = __shfl_up_sync(0xffffffffu, x, o);
        if (lane >= o) x += t;
    }
    __shared__ int wsum[16];
    if (lane == 31) wsum[wid] = x;
    __syncthreads();
    if (wid == 0) {
        int s = (lane < 16) ? wsum[lane] : 0;
#pragma unroll
        for (int o = 1; o < 16; o <<= 1) {
            int t = __shfl_up_sync(0xffffffffu, s, o);
            if (lane >= o) s += t;
        }
        if (lane < 16) wsum[lane] = s;
    }
    __syncthreads();
    int base = (wid > 0) ? wsum[wid - 1] : 0;
    if (i < NN) g_offs[i] = base + x - v;
    if (threadIdx.x == SCAN_BS - 1) g_bsum[blockIdx.x] = base + x;
}

__global__ void k_scan2() {
    int t = threadIdx.x;
    int lane = t & 31, wid = t >> 5;
    int v = (t < NBLK) ? g_bsum[t] : 0;
    int x = v;
#pragma unroll
    for (int o = 1; o < 32; o <<= 1) {
        int tt = __shfl_up_sync(0xffffffffu, x, o);
        if (lane >= o) x += tt;
    }
    __shared__ int wsum[4];
    if (lane == 31) wsum[wid] = x;
    __syncthreads();
    int base = 0;
    for (int w = 0; w < wid; w++) base += wsum[w];
    if (t < NBLK) g_bsum[t] = base + x - v;
}

// scan add-back + dis = rsqrt(1+deg) fused
__global__ __launch_bounds__(SCAN_BS) void k_scan3() {
    int i = blockIdx.x * SCAN_BS + threadIdx.x;
    if (i < NN) {
        int off = g_offs[i] + g_bsum[blockIdx.x];
        g_offs[i] = off;
        g_pos[i] = off;
        g_dis[i] = rsqrtf(1.0f + g_deg[i]);
    }
    if (i == 0) g_offs[NN] = NE;
}

// ---------------- CSR fill with full norm ----------------
__global__ void k_fill(const void* ei, const float* __restrict__ ew) {
    int e = blockIdx.x * blockDim.x + threadIdx.x;
    if (e < NE) {
        int r, c;
        if (g_is64) {
            const long long* p = (const long long*)ei;
            r = (int)p[e];
            c = (int)p[NE + e];
        } else {
            const int* p = (const int*)ei;
            r = p[e];
            c = p[NE + e];
        }
        float nr = g_dis[r] * ew[e] * g_dis[c];
        int idx = atomicAdd(&g_pos[c], 1);
        g_src[idx] = r;
        g_wcsr[idx] = nr;
    }
}

// ---------------- tf32 helpers ----------------
__device__ __forceinline__ void split_tf32(float v, float& hi, float& lo) {
    unsigned uh;
    asm("cvt.rna.tf32.f32 %0, %1;" : "=r"(uh) : "f"(v));
    hi = __uint_as_float(uh);
    float r = v - hi;
    unsigned ul;
    asm("cvt.rna.tf32.f32 %0, %1;" : "=r"(ul) : "f"(r));
    lo = __uint_as_float(ul);
}

__device__ __forceinline__ void mma_tf32(float* d, const unsigned* a, const unsigned* b) {
    asm volatile("mma.sync.aligned.m16n8k8.row.col.f32.tf32.tf32.f32 "
                 "{%0,%1,%2,%3}, {%4,%5,%6,%7}, {%8,%9}, {%0,%1,%2,%3};"
                 : "+f"(d[0]), "+f"(d[1]), "+f"(d[2]), "+f"(d[3])
                 : "r"(a[0]), "r"(a[1]), "r"(a[2]), "r"(a[3]), "r"(b[0]), "r"(b[1]));
}

// ---------------- W pre-split: both weights -> hi/lo planes [128][136] ---------
__global__ void k_wsplit(const float* __restrict__ W1, const float* __restrict__ W2) {
    int f = blockIdx.x * blockDim.x + threadIdx.x;   // float4 slot over 2*128*32
    if (f >= 2 * DD * 32) return;
    int m = f >> 12;            // matrix 0/1
    int rem = f & 4095;         // 128*32
    int k = rem >> 5;
    int c4 = rem & 31;
    const float* W = m ? W2 : W1;
    float4 v = *reinterpret_cast<const float4*>(&W[k * DD + c4 * 4]);
    float h0, l0, h1, l1, h2, l2, h3, l3;
    split_tf32(v.x, h0, l0); split_tf32(v.y, h1, l1);
    split_tf32(v.z, h2, l2); split_tf32(v.w, h3, l3);
    int o = k * 136 + c4 * 4;
    *reinterpret_cast<float4*>(&g_Wh[m][o]) = make_float4(h0, h1, h2, h3);
    *reinterpret_cast<float4*>(&g_Wl[m][o]) = make_float4(l0, l1, l2, l3);
}

// ---------------- GEMM (tf32 split): g_h = X @ W[layer]  (raw, no dis) --------
template<bool RELU>
__global__ __launch_bounds__(256) void k_gemm(const float* __restrict__ Xext, int layer) {
    const float* __restrict__ X = (Xext != nullptr) ? Xext : (const float*)g_a1;
    const float* __restrict__ Wh = g_Wh[layer];
    const float* __restrict__ Wl = g_Wl[layer];

    __shared__ float sXh[128][36], sXl[128][36];
    __shared__ float sWh[32][136], sWl[32][136];

    const int tid = threadIdx.x;
    const int wid = tid >> 5, lane = tid & 31;
    const int g = lane >> 2, tig = lane & 3;
    const int warp_m = wid & 3, warp_n = wid >> 2;
    const int bm0 = blockIdx.x * 128;

    float acc[2][8][4];
#pragma unroll
    for (int mt = 0; mt < 2; mt++)
#pragma unroll
        for (int nt = 0; nt < 8; nt++)
#pragma unroll
            for (int c = 0; c < 4; c++) acc[mt][nt][c] = 0.0f;

    for (int k0 = 0; k0 < DD; k0 += 32) {
        // stage X chunk (split on the fly)
#pragma unroll
        for (int i = 0; i < 4; i++) {
            int f = tid + i * 256;
            int r = f >> 3, c4 = f & 7;
            int row = bm0 + r;
            float4 v = make_float4(0.f, 0.f, 0.f, 0.f);
            if (row < NN) v = *reinterpret_cast<const float4*>(&X[row * DD + k0 + c4 * 4]);
            if (RELU) {
                v.x = fmaxf(v.x, 0.f); v.y = fmaxf(v.y, 0.f);
                v.z = fmaxf(v.z, 0.f); v.w = fmaxf(v.w, 0.f);
            }
            float h0, l0, h1, l1, h2, l2, h3, l3;
            split_tf32(v.x, h0, l0); split_tf32(v.y, h1, l1);
            split_tf32(v.z, h2, l2); split_tf32(v.w, h3, l3);
            int c = c4 * 4;
            sXh[r][c] = h0; sXh[r][c + 1] = h1; sXh[r][c + 2] = h2; sXh[r][c + 3] = h3;
            sXl[r][c] = l0; sXl[r][c + 1] = l1; sXl[r][c + 2] = l2; sXl[r][c + 3] = l3;
        }
        // stage W chunk (pre-split, float4 copies)
#pragma unroll
        for (int i = 0; i < 4; i++) {
            int f = tid + i * 256;
            int k = f >> 5, c4 = f & 31;
            int o = (k0 + k) * 136 + c4 * 4;
            *reinterpret_cast<float4*>(&sWh[k][c4 * 4]) =
                *reinterpret_cast<const float4*>(&Wh[o]);
            *reinterpret_cast<float4*>(&sWl[k][c4 * 4]) =
                *reinterpret_cast<const float4*>(&Wl[o]);
        }
        __syncthreads();

#pragma unroll
        for (int kk = 0; kk < 32; kk += 8) {
            unsigned Ah[2][4], Al[2][4], Bh[8][2], Bl[8][2];
#pragma unroll
            for (int mt = 0; mt < 2; mt++) {
                int r0 = warp_m * 32 + mt * 16 + g;
                Ah[mt][0] = __float_as_uint(sXh[r0][kk + tig]);
                Ah[mt][1] = __float_as_uint(sXh[r0 + 8][kk + tig]);
                Ah[mt][2] = __float_as_uint(sXh[r0][kk + tig + 4]);
                Ah[mt][3] = __float_as_uint(sXh[r0 + 8][kk + tig + 4]);
                Al[mt][0] = __float_as_uint(sXl[r0][kk + tig]);
                Al[mt][1] = __float_as_uint(sXl[r0 + 8][kk + tig]);
                Al[mt][2] = __float_as_uint(sXl[r0][kk + tig + 4]);
                Al[mt][3] = __float_as_uint(sXl[r0 + 8][kk + tig + 4]);
            }
#pragma unroll
            for (int nt = 0; nt < 8; nt++) {
                int n = warp_n * 64 + nt * 8 + g;
                Bh[nt][0] = __float_as_uint(sWh[kk + tig][n]);
                Bh[nt][1] = __float_as_uint(sWh[kk + tig + 4][n]);
                Bl[nt][0] = __float_as_uint(sWl[kk + tig][n]);
                Bl[nt][1] = __float_as_uint(sWl[kk + tig + 4][n]);
            }
#pragma unroll
            for (int mt = 0; mt < 2; mt++)
#pragma unroll
                for (int nt = 0; nt < 8; nt++) {
                    mma_tf32(acc[mt][nt], Ah[mt], Bh[nt]);
                    mma_tf32(acc[mt][nt], Ah[mt], Bl[nt]);
                    mma_tf32(acc[mt][nt], Al[mt], Bh[nt]);
                }
        }
        __syncthreads();
    }

#pragma unroll
    for (int mt = 0; mt < 2; mt++) {
        int r0 = bm0 + warp_m * 32 + mt * 16 + g;
        int r1 = r0 + 8;
#pragma unroll
        for (int nt = 0; nt < 8; nt++) {
            int col = warp_n * 64 + nt * 8 + tig * 2;
            if (r0 < NN)
                *reinterpret_cast<float2*>(&g_h[r0 * DD + col]) =
                    make_float2(acc[mt][nt][0], acc[mt][nt][1]);
            if (r1 < NN)
                *reinterpret_cast<float2*>(&g_h[r1 * DD + col]) =
                    make_float2(acc[mt][nt][2], acc[mt][nt][3]);
        }
    }
}

// ---------------- aggregate: out = b + dis^2*H_i + sum nrm_j*H_src ------------
__global__ __launch_bounds__(256) void k_agg(const float* __restrict__ b,
                                             float* __restrict__ outext) {
    float* __restrict__ out = (outext != nullptr) ? outext : (float*)g_a1;
    const float* __restrict__ h = (const float*)g_h;

    int node = blockIdx.x * 8 + (threadIdx.x >> 5);
    int lane = threadIdx.x & 31;
    if (node >= NN) return;

    float s = g_dis[node];
    float s2 = s * s;
    float4 hv = *reinterpret_cast<const float4*>(&h[node * DD + lane * 4]);
    float ax = s2 * hv.x, ay = s2 * hv.y, az = s2 * hv.z, aw = s2 * hv.w;

    int j = g_offs[node];
    int end = g_offs[node + 1];

    for (; j + 3 < end; j += 4) {
        int s0 = g_src[j],     s1 = g_src[j + 1];
        int sA = g_src[j + 2], sB = g_src[j + 3];
        float n0 = g_wcsr[j],     n1 = g_wcsr[j + 1];
        float n2 = g_wcsr[j + 2], n3 = g_wcsr[j + 3];
        float4 v0 = *reinterpret_cast<const float4*>(&h[s0 * DD + lane * 4]);
        float4 v1 = *reinterpret_cast<const float4*>(&h[s1 * DD + lane * 4]);
        float4 v2 = *reinterpret_cast<const float4*>(&h[sA * DD + lane * 4]);
        float4 v3 = *reinterpret_cast<const float4*>(&h[sB * DD + lane * 4]);
        ax += n0 * v0.x + n1 * v1.x + n2 * v2.x + n3 * v3.x;
        ay += n0 * v0.y + n1 * v1.y + n2 * v2.y + n3 * v3.y;
        az += n0 * v0.z + n1 * v1.z + n2 * v2.z + n3 * v3.z;
        aw += n0 * v0.w + n1 * v1.w + n2 * v2.w + n3 * v3.w;
    }
    for (; j < end; j++) {
        int s0 = g_src[j];
        float n0 = g_wcsr[j];
        float4 v0 = *reinterpret_cast<const float4*>(&h[s0 * DD + lane * 4]);
        ax += n0 * v0.x; ay += n0 * v0.y; az += n0 * v0.z; aw += n0 * v0.w;
    }

    float4 bv = *reinterpret_cast<const float4*>(&b[lane * 4]);
    *reinterpret_cast<float4*>(&out[node * DD + lane * 4]) =
        make_float4(bv.x + ax, bv.y + ay, bv.z + az, bv.w + aw);
}

// ---------------- launch: fork prep (stream B) || wsplit+gemm1 (stream 0) ------
extern "C" void kernel_launch(void* const* d_in, const int* in_sizes, int n_in,
                              void* d_out, int out_size) {
    const float* x  = (const float*)d_in[0];
    const void*  ei = d_in[1];
    const float* ew = (const float*)d_in[2];
    const float* W1 = (const float*)d_in[3];
    const float* b1 = (const float*)d_in[4];
    const float* W2 = (const float*)d_in[5];
    const float* b2 = (const float*)d_in[6];
    float* out = (float*)d_out;

    // lazily created once (on the non-captured correctness call); reused thereafter.
    static cudaStream_t sB = nullptr;
    static cudaEvent_t evFork = nullptr, evPrep = nullptr;
    if (sB == nullptr) {
        cudaStreamCreateWithFlags(&sB, cudaStreamNonBlocking);
        cudaEventCreateWithFlags(&evFork, cudaEventDisableTiming);
        cudaEventCreateWithFlags(&evPrep, cudaEventDisableTiming);
    }

    const int T = 256;
    const int gN = (NN + T - 1) / T;
    const int gE = (NE + T - 1) / T;
    const int gG = (NN + 127) / 128;
    const int gA = (NN + 7) / 8;
    const int gW = (2 * DD * 32 + T - 1) / T;

    // fork: prep chain on sB
    cudaEventRecord(evFork, 0);
    cudaStreamWaitEvent(sB, evFork, 0);
    k_prep0<<<gN, T, 0, sB>>>(ei);
    k_count<<<gE, T, 0, sB>>>(ei, ew);
    k_scan1<<<NBLK, SCAN_BS, 0, sB>>>();
    k_scan2<<<1, 128, 0, sB>>>();
    k_scan3<<<NBLK, SCAN_BS, 0, sB>>>();
    k_fill<<<gE, T, 0, sB>>>(ei, ew);
    cudaEventRecord(evPrep, sB);

    // concurrent: weight split + layer-1 GEMM (no prep dependency)
    k_wsplit<<<gW, T>>>(W1, W2);
    k_gemm<false><<<gG, 256>>>(x, 0);

    // join, then serial tail
    cudaStreamWaitEvent(0, evPrep, 0);
    k_agg<<<gA, T>>>(b1, nullptr);
    k_gemm<true><<<gG, 256>>>(nullptr, 1);
    k_agg<<<gA, T>>>(b2, out);
}